// round 1
// baseline (speedup 1.0000x reference)
#include <cuda_runtime.h>

#define B_ 4
#define T_ 2048
#define C_ 1024
#define H_ 16
#define D_ 64
#define M_ (B_*T_)   // 8192
#define SS 76        // Ss row stride (bank-rotating, 16B-aligned)

// Scratch (allocation-free rule: __device__ globals)
__device__ float g_q[(size_t)B_*H_*T_*D_];
__device__ float g_k[(size_t)B_*H_*T_*D_];
__device__ float g_v[(size_t)B_*H_*T_*D_];
__device__ float g_y[(size_t)B_*T_*C_];

// ---------------------------------------------------------------------------
// GEMM: Out = A[M,1024] @ W[1024,1024] + bias, 64x64 tile, BK=16, 256 thr
// DST: 0->g_q, 1->g_k, 2->g_v (head-scatter layout), 3->Out param (plain),
//      DST==3 reads A from g_y.
// ---------------------------------------------------------------------------
template<int DST>
__global__ __launch_bounds__(256)
void gemm_bias_k(const float* __restrict__ Xin, const float* __restrict__ W,
                 const float* __restrict__ bias, float* __restrict__ Out)
{
    __shared__ float As[16][64];   // [k][m] (transposed)
    __shared__ float Bs[16][64];   // [k][n]

    const float* A = (DST == 3) ? (const float*)g_y : Xin;
    float* O = (DST == 0) ? g_q : (DST == 1) ? g_k : (DST == 2) ? g_v : Out;

    const int tid = threadIdx.x;
    const int m0 = blockIdx.x * 64;
    const int n0 = blockIdx.y * 64;
    const int tx = tid & 15;       // m micro-tile group
    const int ty = tid >> 4;       // n micro-tile group
    const int lm = tid >> 2;       // A-load row
    const int lk = (tid & 3) * 4;  // A-load k offset
    const int bk = tid >> 4;       // B-load k row
    const int bn = (tid & 15) * 4; // B-load col

    float acc[4][4];
#pragma unroll
    for (int i = 0; i < 4; i++)
#pragma unroll
        for (int j = 0; j < 4; j++) acc[i][j] = 0.f;

    for (int k0 = 0; k0 < C_; k0 += 16) {
        float4 av = *(const float4*)(A + (size_t)(m0 + lm) * C_ + k0 + lk);
        As[lk + 0][lm] = av.x;
        As[lk + 1][lm] = av.y;
        As[lk + 2][lm] = av.z;
        As[lk + 3][lm] = av.w;
        float4 bv = *(const float4*)(W + (size_t)(k0 + bk) * C_ + n0 + bn);
        *(float4*)&Bs[bk][bn] = bv;
        __syncthreads();
#pragma unroll
        for (int kk = 0; kk < 16; kk++) {
            float4 a = *(const float4*)&As[kk][tx * 4];
            float4 b = *(const float4*)&Bs[kk][ty * 4];
            float am[4] = {a.x, a.y, a.z, a.w};
            float bb[4] = {b.x, b.y, b.z, b.w};
#pragma unroll
            for (int i = 0; i < 4; i++)
#pragma unroll
                for (int j = 0; j < 4; j++) acc[i][j] += am[i] * bb[j];
        }
        __syncthreads();
    }

    float4 bv = *(const float4*)(bias + n0 + ty * 4);
    float badd[4] = {bv.x, bv.y, bv.z, bv.w};
#pragma unroll
    for (int i = 0; i < 4; i++) {
        int m = m0 + tx * 4 + i;
        float4 o;
        o.x = acc[i][0] + badd[0];
        o.y = acc[i][1] + badd[1];
        o.z = acc[i][2] + badd[2];
        o.w = acc[i][3] + badd[3];
        if (DST == 3) {
            *(float4*)(O + (size_t)m * C_ + n0 + ty * 4) = o;
        } else {
            int b = m >> 11;          // T_ = 2048
            int t = m & (T_ - 1);
            int h = n0 >> 6;          // n0 multiple of 64, D_=64
            int d = ty * 4;
            *(float4*)(O + (((size_t)(b * H_ + h)) * T_ + t) * D_ + d) = o;
        }
    }
}

// ---------------------------------------------------------------------------
// Causal flash attention: 64-query x 64-key tiles, D=64, fp32, online softmax
// grid (T_/64, B_*H_), 256 threads
// ---------------------------------------------------------------------------
__global__ __launch_bounds__(256)
void attn_k()
{
    extern __shared__ float sm[];
    float* Qs = sm;               // [d][m] transposed, 64x64
    float* Ks = Qs + 4096;        // [d][n] transposed
    float* Vs = Ks + 4096;        // [n][d] row-major
    float* Ss = Vs + 4096;        // [64][SS]

    const int tid = threadIdx.x;
    const int qb  = blockIdx.x;
    const int bh  = blockIdx.y;
    const float* Qg = g_q + (size_t)bh * T_ * D_;
    const float* Kg = g_k + (size_t)bh * T_ * D_;
    const float* Vg = g_v + (size_t)bh * T_ * D_;

    const int lr = tid >> 2;        // load row 0..63
    const int lc = (tid & 3) * 16;  // load col base

    // Q tile -> smem transposed
#pragma unroll
    for (int s = 0; s < 4; s++) {
        float4 v = *(const float4*)(Qg + (size_t)(qb * 64 + lr) * D_ + lc + s * 4);
        Qs[(lc + s * 4 + 0) * 64 + lr] = v.x;
        Qs[(lc + s * 4 + 1) * 64 + lr] = v.y;
        Qs[(lc + s * 4 + 2) * 64 + lr] = v.z;
        Qs[(lc + s * 4 + 3) * 64 + lr] = v.w;
    }

    const int tx = tid & 15, ty = tid >> 4;  // phase-A mapping
    const int row = tid >> 2, sub = tid & 3; // phase-B mapping (4-lane teams)

    float m_i = -1e30f, l_i = 0.f;
    float4 o[4];
#pragma unroll
    for (int i = 0; i < 4; i++) o[i] = make_float4(0.f, 0.f, 0.f, 0.f);

    __syncthreads();

    for (int kb = 0; kb <= qb; kb++) {
        // K (transposed) + V tiles
#pragma unroll
        for (int s = 0; s < 4; s++) {
            float4 kv = *(const float4*)(Kg + (size_t)(kb * 64 + lr) * D_ + lc + s * 4);
            Ks[(lc + s * 4 + 0) * 64 + lr] = kv.x;
            Ks[(lc + s * 4 + 1) * 64 + lr] = kv.y;
            Ks[(lc + s * 4 + 2) * 64 + lr] = kv.z;
            Ks[(lc + s * 4 + 3) * 64 + lr] = kv.w;
            float4 vv = *(const float4*)(Vg + (size_t)(kb * 64 + lr) * D_ + lc + s * 4);
            *(float4*)&Vs[lr * 64 + lc + s * 4] = vv;
        }
        __syncthreads();

        // Phase A: S = (Q K^T) * scale with causal mask, into Ss
        {
            float acc[4][4];
#pragma unroll
            for (int i = 0; i < 4; i++)
#pragma unroll
                for (int j = 0; j < 4; j++) acc[i][j] = 0.f;
#pragma unroll 8
            for (int d = 0; d < 64; d++) {
                float4 a = *(const float4*)&Qs[d * 64 + tx * 4];
                float4 b = *(const float4*)&Ks[d * 64 + ty * 4];
                float am[4] = {a.x, a.y, a.z, a.w};
                float bb[4] = {b.x, b.y, b.z, b.w};
#pragma unroll
                for (int i = 0; i < 4; i++)
#pragma unroll
                    for (int j = 0; j < 4; j++) acc[i][j] += am[i] * bb[j];
            }
#pragma unroll
            for (int i = 0; i < 4; i++) {
                int r  = tx * 4 + i;
                int rg = qb * 64 + r;
                float s4[4];
#pragma unroll
                for (int j = 0; j < 4; j++) {
                    float s = acc[i][j] * 0.125f;  // 1/sqrt(64)
                    int cg = kb * 64 + ty * 4 + j;
                    if (kb == qb && cg > rg) s = -1e30f;
                    s4[j] = s;
                }
                float4 sv = make_float4(s4[0], s4[1], s4[2], s4[3]);
                *(float4*)&Ss[r * SS + ty * 4] = sv;
            }
        }
        __syncthreads();

        // Phase B: online softmax + O accumulation (4-lane row teams)
        {
            float* srow = Ss + row * SS + sub * 16;
            float sv[16];
            float mt = -1e30f;
#pragma unroll
            for (int j = 0; j < 16; j++) {
                sv[j] = srow[j];
                mt = fmaxf(mt, sv[j]);
            }
            mt = fmaxf(mt, __shfl_xor_sync(0xffffffffu, mt, 1));
            mt = fmaxf(mt, __shfl_xor_sync(0xffffffffu, mt, 2));
            float mnew  = fmaxf(m_i, mt);
            float alpha = __expf(m_i - mnew);
            float lsum  = 0.f;
#pragma unroll
            for (int j = 0; j < 16; j++) {
                float p = __expf(sv[j] - mnew);
                srow[j] = p;
                lsum += p;
            }
            lsum += __shfl_xor_sync(0xffffffffu, lsum, 1);
            lsum += __shfl_xor_sync(0xffffffffu, lsum, 2);
            l_i = l_i * alpha + lsum;
            m_i = mnew;
#pragma unroll
            for (int i = 0; i < 4; i++) {
                o[i].x *= alpha; o[i].y *= alpha; o[i].z *= alpha; o[i].w *= alpha;
            }
            __syncwarp();
            const float4* Vs4 = (const float4*)Vs;
#pragma unroll 8
            for (int j = 0; j < 64; j++) {
                float p = Ss[row * SS + j];
#pragma unroll
                for (int i = 0; i < 4; i++) {
                    float4 v = Vs4[j * 16 + sub * 4 + i];
                    o[i].x += p * v.x;
                    o[i].y += p * v.y;
                    o[i].z += p * v.z;
                    o[i].w += p * v.w;
                }
            }
        }
        __syncthreads();
    }

    // normalize + write to g_y in [B,T,C] layout
    float inv = 1.f / l_i;
    int b = bh >> 4, h = bh & 15;
    int t = qb * 64 + row;
    float* outp = g_y + ((size_t)b * T_ + t) * C_ + h * D_ + sub * 16;
#pragma unroll
    for (int i = 0; i < 4; i++) {
        float4 v = o[i];
        v.x *= inv; v.y *= inv; v.z *= inv; v.w *= inv;
        *(float4*)(outp + i * 4) = v;
    }
}

// ---------------------------------------------------------------------------
extern "C" void kernel_launch(void* const* d_in, const int* in_sizes, int n_in,
                              void* d_out, int out_size)
{
    const float* x  = (const float*)d_in[0];
    const float* Wk = (const float*)d_in[1];
    const float* bk = (const float*)d_in[2];
    const float* Wq = (const float*)d_in[3];
    const float* bq = (const float*)d_in[4];
    const float* Wv = (const float*)d_in[5];
    const float* bv = (const float*)d_in[6];
    const float* Wp = (const float*)d_in[7];
    const float* bp = (const float*)d_in[8];
    float* out = (float*)d_out;

    dim3 gg(M_ / 64, C_ / 64);

    gemm_bias_k<0><<<gg, 256>>>(x, Wq, bq, nullptr);
    gemm_bias_k<1><<<gg, 256>>>(x, Wk, bk, nullptr);
    gemm_bias_k<2><<<gg, 256>>>(x, Wv, bv, nullptr);

    const int smem_attn = (3 * 4096 + 64 * SS) * sizeof(float);  // 68608 B
    cudaFuncSetAttribute(attn_k, cudaFuncAttributeMaxDynamicSharedMemorySize, smem_attn);
    attn_k<<<dim3(T_ / 64, B_ * H_), 256, smem_attn>>>();

    gemm_bias_k<3><<<gg, 256>>>(nullptr, Wp, bp, out);
}

// round 7
// speedup vs baseline: 1.3049x; 1.3049x over previous
#include <cuda_runtime.h>
#include <cuda_bf16.h>
#include <cstdint>

#define B_ 4
#define T_ 2048
#define C_ 1024
#define H_ 16
#define D_ 64
#define M_ (B_*T_)   // 8192
#define SS 76        // attn Ss row stride

// ---------------------------------------------------------------------------
// Scratch (__device__ globals; referenced ONLY from device code — passing
// these from host as kernel args yields the host shadow address (ATS-readable
// zeros on GB300), which was the round-5/6 bug)
// ---------------------------------------------------------------------------
__device__ float g_q[(size_t)B_*H_*T_*D_];
__device__ float g_k[(size_t)B_*H_*T_*D_];
__device__ float g_v[(size_t)B_*H_*T_*D_];
__device__ float g_y[(size_t)B_*T_*C_];
__device__ __align__(16) unsigned short g_xhi[(size_t)M_*C_];
__device__ __align__(16) unsigned short g_xlo[(size_t)M_*C_];
__device__ __align__(16) unsigned short g_whiT[(size_t)4*C_*C_];  // [slot][n][k]
__device__ __align__(16) unsigned short g_wloT[(size_t)4*C_*C_];

// ---------------------------------------------------------------------------
// Base-target PTX helpers: ldmatrix / mma.sync / cp.async only
// ---------------------------------------------------------------------------
__device__ __forceinline__ uint32_t s2u(const void* p) {
    uint32_t a;
    asm("{ .reg .u64 t; cvta.to.shared.u64 t, %1; cvt.u32.u64 %0, t; }" : "=r"(a) : "l"(p));
    return a;
}

__device__ __forceinline__ void ldsm_x4(uint32_t addr, uint32_t* r) {
    asm volatile("ldmatrix.sync.aligned.m8n8.x4.shared.b16 {%0,%1,%2,%3}, [%4];"
                 : "=r"(r[0]), "=r"(r[1]), "=r"(r[2]), "=r"(r[3]) : "r"(addr));
}

__device__ __forceinline__ void mma_bf16(float* c, const uint32_t* a, uint32_t b0, uint32_t b1) {
    asm("mma.sync.aligned.m16n8k16.row.col.f32.bf16.bf16.f32 "
        "{%0,%1,%2,%3}, {%4,%5,%6,%7}, {%8,%9}, {%0,%1,%2,%3};"
        : "+f"(c[0]), "+f"(c[1]), "+f"(c[2]), "+f"(c[3])
        : "r"(a[0]), "r"(a[1]), "r"(a[2]), "r"(a[3]), "r"(b0), "r"(b1));
}

__device__ __forceinline__ void cp16(uint32_t saddr, const void* g) {
    asm volatile("cp.async.cg.shared.global [%0], [%1], 16;" :: "r"(saddr), "l"(g));
}

// pack two floats to bf16x2: low 16 bits = lo arg, high 16 bits = hi arg
__device__ __forceinline__ uint32_t packbf(float lo, float hi) {
    uint32_t r;
    asm("cvt.rn.bf16x2.f32 %0, %1, %2;" : "=r"(r) : "f"(hi), "f"(lo));
    return r;
}

// ---------------------------------------------------------------------------
// Conversion pre-passes. SRC=0: read from param (harness pointer).
// SRC=1: read g_y (device symbol, bound in device code).
// ---------------------------------------------------------------------------
template<int SRC>
__global__ __launch_bounds__(256) void conv_x_k(const float* __restrict__ in, int n4)
{
    int i = blockIdx.x * blockDim.x + threadIdx.x;
    if (i >= n4) return;
    const float* src = (SRC == 1) ? (const float*)g_y : in;
    float4 v = ((const float4*)src)[i];
    uint32_t h0 = packbf(v.x, v.y);
    uint32_t h1 = packbf(v.z, v.w);
    float r0 = v.x - __uint_as_float(h0 << 16);
    float r1 = v.y - __uint_as_float(h0 & 0xFFFF0000u);
    float r2 = v.z - __uint_as_float(h1 << 16);
    float r3 = v.w - __uint_as_float(h1 & 0xFFFF0000u);
    ((uint2*)g_xhi)[i] = make_uint2(h0, h1);
    ((uint2*)g_xlo)[i] = make_uint2(packbf(r0, r1), packbf(r2, r3));
}

// W[k][n] -> WT hi/lo [n][k]
__global__ void conv_w_t_k(const float* __restrict__ W, int slot)
{
    __shared__ float tile[32][33];
    const int n0 = blockIdx.x * 32, k0 = blockIdx.y * 32;
    const int tx = threadIdx.x, ty = threadIdx.y;
    unsigned short* hiT = g_whiT + (size_t)slot * C_ * C_;
    unsigned short* loT = g_wloT + (size_t)slot * C_ * C_;
    for (int r = ty; r < 32; r += 8)
        tile[r][tx] = W[(size_t)(k0 + r) * C_ + n0 + tx];
    __syncthreads();
    for (int r = ty; r < 32; r += 8) {
        float v = tile[tx][r];  // W[k0+tx][n0+r]
        __nv_bfloat16 h = __float2bfloat16_rn(v);
        float res = v - __bfloat162float(h);
        size_t o = (size_t)(n0 + r) * C_ + k0 + tx;
        hiT[o] = __bfloat16_as_ushort(h);
        loT[o] = __bfloat16_as_ushort(__float2bfloat16_rn(res));
    }
}

// ---------------------------------------------------------------------------
// GEMM via mma.sync: C[128x128] = A[128xK] * B^T + bias, fp32 outputs.
// A = g_xhi/g_xlo [m][k] (device symbols); B = g_w{hi,lo}T slot DST [n][k].
// 256 thr = 8 warps (2x4). DST 0/1/2: fp32 head-scatter to g_q/g_k/g_v.
// DST 3: fp32 plain to OutP. smem: 2 stages x 4 ops x 128 rows x 80B.
// ---------------------------------------------------------------------------
template<int DST>
__global__ __launch_bounds__(256)
void gemm_mma(const float* __restrict__ bias, float* __restrict__ OutP)
{
    extern __shared__ __align__(16) char sm[];
    const uint32_t smb = s2u(sm);
    const int tid = threadIdx.x, lane = tid & 31, wid = tid >> 5;
    const int warp_m = wid >> 2, warp_n = wid & 3;
    const int m0 = blockIdx.x * 128, n0 = blockIdx.y * 128;

    const unsigned short* Ahi = g_xhi;                 // device-side binding
    const unsigned short* Alo = g_xlo;
    const unsigned short* Bhi = g_whiT + (size_t)DST * C_ * C_;
    const unsigned short* Blo = g_wloT + (size_t)DST * C_ * C_;

    const unsigned short* gsrc[8];
    uint32_t sdst[8];
#pragma unroll
    for (int i = 0; i < 8; i++) {
        const int op  = i >> 1;                       // 0 Ahi,1 Alo,2 Bhi,3 Blo
        const int row = (tid >> 2) + (i & 1) * 64;
        const int seg = tid & 3;
        const unsigned short* base = (op == 0) ? Ahi : (op == 1) ? Alo : (op == 2) ? Bhi : Blo;
        const int grow = ((op < 2) ? m0 : n0) + row;
        gsrc[i] = base + (size_t)grow * C_ + seg * 8;
        sdst[i] = smb + op * 10240 + row * 80 + seg * 16;
    }

    float c[4][4][4];
#pragma unroll
    for (int mt = 0; mt < 4; mt++)
#pragma unroll
        for (int nt = 0; nt < 4; nt++)
#pragma unroll
            for (int e = 0; e < 4; e++) c[mt][nt][e] = 0.f;

#pragma unroll
    for (int i = 0; i < 8; i++) cp16(sdst[i], gsrc[i]);
    asm volatile("cp.async.commit_group;");

    for (int it = 0; it < 32; ++it) {
        const int st = it & 1;
        if (it + 1 < 32) {
            const int ns = (it + 1) & 1;
#pragma unroll
            for (int i = 0; i < 8; i++) cp16(sdst[i] + ns * 40960, gsrc[i] + (it + 1) * 32);
            asm volatile("cp.async.commit_group;");
            asm volatile("cp.async.wait_group 1;");
        } else {
            asm volatile("cp.async.wait_group 0;");
        }
        __syncthreads();

        const uint32_t sb = smb + st * 40960;
#pragma unroll
        for (int kk = 0; kk < 2; kk++) {
            uint32_t ah[4][4], al[4][4], bh[4][2], bl[4][2];
#pragma unroll
            for (int mt = 0; mt < 4; mt++) {
                int row = warp_m * 64 + mt * 16 + (lane & 7) + ((lane >> 3) & 1) * 8;
                uint32_t byte = (uint32_t)(row * 80 + kk * 32 + (lane >> 4) * 16);
                ldsm_x4(sb + byte, ah[mt]);
                ldsm_x4(sb + 10240 + byte, al[mt]);
            }
#pragma unroll
            for (int p = 0; p < 2; p++) {
                int row = warp_n * 32 + p * 16 + (lane & 7) + ((lane >> 3) & 1) * 8;
                uint32_t byte = (uint32_t)(row * 80 + kk * 32 + (lane >> 4) * 16);
                uint32_t r[4], u[4];
                ldsm_x4(sb + 20480 + byte, r);
                ldsm_x4(sb + 30720 + byte, u);
                bh[2*p][0] = r[0]; bh[2*p][1] = r[2];
                bh[2*p+1][0] = r[1]; bh[2*p+1][1] = r[3];
                bl[2*p][0] = u[0]; bl[2*p][1] = u[2];
                bl[2*p+1][0] = u[1]; bl[2*p+1][1] = u[3];
            }
#pragma unroll
            for (int mt = 0; mt < 4; mt++)
#pragma unroll
                for (int nt = 0; nt < 4; nt++) {
                    mma_bf16(c[mt][nt], ah[mt], bh[nt][0], bh[nt][1]);
                    mma_bf16(c[mt][nt], ah[mt], bl[nt][0], bl[nt][1]);
                    mma_bf16(c[mt][nt], al[mt], bh[nt][0], bh[nt][1]);
                }
        }
        __syncthreads();
    }

    // fp32 epilogue
#pragma unroll
    for (int mt = 0; mt < 4; mt++) {
        const int r = m0 + warp_m * 64 + mt * 16 + (lane >> 2);
#pragma unroll
        for (int nt = 0; nt < 4; nt++) {
            const int col = n0 + warp_n * 32 + nt * 8 + (lane & 3) * 2;
            const float bb0 = bias[col], bb1 = bias[col + 1];
#pragma unroll
            for (int half = 0; half < 2; half++) {
                const int m = r + half * 8;
                float v0 = c[mt][nt][half * 2 + 0] + bb0;
                float v1 = c[mt][nt][half * 2 + 1] + bb1;
                if (DST == 3) {
                    *(float2*)(OutP + (size_t)m * C_ + col) = make_float2(v0, v1);
                } else {
                    float* O = (DST == 0) ? g_q : (DST == 1) ? g_k : g_v;
                    const int b = m >> 11, t = m & (T_ - 1);
                    const int h = col >> 6, d = col & 63;
                    *(float2*)(O + (((size_t)(b * H_ + h)) * T_ + t) * D_ + d) = make_float2(v0, v1);
                }
            }
        }
    }
}

// ---------------------------------------------------------------------------
// Causal flash attention (round-1 SIMT version, known-good, verbatim)
// ---------------------------------------------------------------------------
__global__ __launch_bounds__(256)
void attn_k()
{
    extern __shared__ float smf[];
    float* Qs = smf;
    float* Ks = Qs + 4096;
    float* Vs = Ks + 4096;
    float* Ss = Vs + 4096;

    const int tid = threadIdx.x;
    const int qb  = blockIdx.x;
    const int bh  = blockIdx.y;
    const float* Qg = g_q + (size_t)bh * T_ * D_;
    const float* Kg = g_k + (size_t)bh * T_ * D_;
    const float* Vg = g_v + (size_t)bh * T_ * D_;

    const int lr = tid >> 2;
    const int lc = (tid & 3) * 16;

#pragma unroll
    for (int s = 0; s < 4; s++) {
        float4 v = *(const float4*)(Qg + (size_t)(qb * 64 + lr) * D_ + lc + s * 4);
        Qs[(lc + s * 4 + 0) * 64 + lr] = v.x;
        Qs[(lc + s * 4 + 1) * 64 + lr] = v.y;
        Qs[(lc + s * 4 + 2) * 64 + lr] = v.z;
        Qs[(lc + s * 4 + 3) * 64 + lr] = v.w;
    }

    const int tx = tid & 15, ty = tid >> 4;
    const int row = tid >> 2, sub = tid & 3;

    float m_i = -1e30f, l_i = 0.f;
    float4 o[4];
#pragma unroll
    for (int i = 0; i < 4; i++) o[i] = make_float4(0.f, 0.f, 0.f, 0.f);

    __syncthreads();

    for (int kb = 0; kb <= qb; kb++) {
#pragma unroll
        for (int s = 0; s < 4; s++) {
            float4 kv = *(const float4*)(Kg + (size_t)(kb * 64 + lr) * D_ + lc + s * 4);
            Ks[(lc + s * 4 + 0) * 64 + lr] = kv.x;
            Ks[(lc + s * 4 + 1) * 64 + lr] = kv.y;
            Ks[(lc + s * 4 + 2) * 64 + lr] = kv.z;
            Ks[(lc + s * 4 + 3) * 64 + lr] = kv.w;
            float4 vv = *(const float4*)(Vg + (size_t)(kb * 64 + lr) * D_ + lc + s * 4);
            *(float4*)&Vs[lr * 64 + lc + s * 4] = vv;
        }
        __syncthreads();

        {
            float acc[4][4];
#pragma unroll
            for (int i = 0; i < 4; i++)
#pragma unroll
                for (int j = 0; j < 4; j++) acc[i][j] = 0.f;
#pragma unroll 8
            for (int d = 0; d < 64; d++) {
                float4 a = *(const float4*)&Qs[d * 64 + tx * 4];
                float4 b = *(const float4*)&Ks[d * 64 + ty * 4];
                float am[4] = {a.x, a.y, a.z, a.w};
                float bb[4] = {b.x, b.y, b.z, b.w};
#pragma unroll
                for (int i = 0; i < 4; i++)
#pragma unroll
                    for (int j = 0; j < 4; j++) acc[i][j] += am[i] * bb[j];
            }
#pragma unroll
            for (int i = 0; i < 4; i++) {
                int r  = tx * 4 + i;
                int rg = qb * 64 + r;
                float s4[4];
#pragma unroll
                for (int j = 0; j < 4; j++) {
                    float s = acc[i][j] * 0.125f;
                    int cg = kb * 64 + ty * 4 + j;
                    if (kb == qb && cg > rg) s = -1e30f;
                    s4[j] = s;
                }
                float4 sv = make_float4(s4[0], s4[1], s4[2], s4[3]);
                *(float4*)&Ss[r * SS + ty * 4] = sv;
            }
        }
        __syncthreads();

        {
            float* srow = Ss + row * SS + sub * 16;
            float sv[16];
            float mt = -1e30f;
#pragma unroll
            for (int j = 0; j < 16; j++) {
                sv[j] = srow[j];
                mt = fmaxf(mt, sv[j]);
            }
            mt = fmaxf(mt, __shfl_xor_sync(0xffffffffu, mt, 1));
            mt = fmaxf(mt, __shfl_xor_sync(0xffffffffu, mt, 2));
            float mnew  = fmaxf(m_i, mt);
            float alpha = __expf(m_i - mnew);
            float lsum  = 0.f;
#pragma unroll
            for (int j = 0; j < 16; j++) {
                float p = __expf(sv[j] - mnew);
                srow[j] = p;
                lsum += p;
            }
            lsum += __shfl_xor_sync(0xffffffffu, lsum, 1);
            lsum += __shfl_xor_sync(0xffffffffu, lsum, 2);
            l_i = l_i * alpha + lsum;
            m_i = mnew;
#pragma unroll
            for (int i = 0; i < 4; i++) {
                o[i].x *= alpha; o[i].y *= alpha; o[i].z *= alpha; o[i].w *= alpha;
            }
            __syncwarp();
            const float4* Vs4 = (const float4*)Vs;
#pragma unroll 8
            for (int j = 0; j < 64; j++) {
                float p = Ss[row * SS + j];
#pragma unroll
                for (int i = 0; i < 4; i++) {
                    float4 v = Vs4[j * 16 + sub * 4 + i];
                    o[i].x += p * v.x;
                    o[i].y += p * v.y;
                    o[i].z += p * v.z;
                    o[i].w += p * v.w;
                }
            }
        }
        __syncthreads();
    }

    float inv = 1.f / l_i;
    int b = bh >> 4, h = bh & 15;
    int t = qb * 64 + row;
    float* outp = g_y + ((size_t)b * T_ + t) * C_ + h * D_ + sub * 16;
#pragma unroll
    for (int i = 0; i < 4; i++) {
        float4 v = o[i];
        v.x *= inv; v.y *= inv; v.z *= inv; v.w *= inv;
        *(float4*)(outp + i * 4) = v;
    }
}

// ---------------------------------------------------------------------------
extern "C" void kernel_launch(void* const* d_in, const int* in_sizes, int n_in,
                              void* d_out, int out_size)
{
    const float* x  = (const float*)d_in[0];
    const float* Wk = (const float*)d_in[1];
    const float* bk = (const float*)d_in[2];
    const float* Wq = (const float*)d_in[3];
    const float* bq = (const float*)d_in[4];
    const float* Wv = (const float*)d_in[5];
    const float* bv = (const float*)d_in[6];
    const float* Wp = (const float*)d_in[7];
    const float* bp = (const float*)d_in[8];
    float* out = (float*)d_out;

    const int n4 = M_ * C_ / 4;
    conv_x_k<0><<<(n4 + 255) / 256, 256>>>(x, n4);

    dim3 tg(32, 32), tb(32, 8);
    conv_w_t_k<<<tg, tb>>>(Wq, 0);
    conv_w_t_k<<<tg, tb>>>(Wk, 1);
    conv_w_t_k<<<tg, tb>>>(Wv, 2);
    conv_w_t_k<<<tg, tb>>>(Wp, 3);

    const int smem_g = 81920;
    cudaFuncSetAttribute(gemm_mma<0>, cudaFuncAttributeMaxDynamicSharedMemorySize, smem_g);
    cudaFuncSetAttribute(gemm_mma<1>, cudaFuncAttributeMaxDynamicSharedMemorySize, smem_g);
    cudaFuncSetAttribute(gemm_mma<2>, cudaFuncAttributeMaxDynamicSharedMemorySize, smem_g);
    cudaFuncSetAttribute(gemm_mma<3>, cudaFuncAttributeMaxDynamicSharedMemorySize, smem_g);

    dim3 gg(M_ / 128, C_ / 128);
    gemm_mma<0><<<gg, 256, smem_g>>>(bq, nullptr);
    gemm_mma<1><<<gg, 256, smem_g>>>(bk, nullptr);
    gemm_mma<2><<<gg, 256, smem_g>>>(bv, nullptr);

    const int smem_attn = (3 * 4096 + 64 * SS) * sizeof(float);
    cudaFuncSetAttribute(attn_k, cudaFuncAttributeMaxDynamicSharedMemorySize, smem_attn);
    attn_k<<<dim3(T_ / 64, B_ * H_), 256, smem_attn>>>();

    conv_x_k<1><<<(n4 + 255) / 256, 256>>>(nullptr, n4);
    gemm_mma<3><<<gg, 256, smem_g>>>(bp, out);
}

// round 8
// speedup vs baseline: 4.2923x; 3.2893x over previous
#include <cuda_runtime.h>
#include <cuda_bf16.h>
#include <cstdint>

#define B_ 4
#define T_ 2048
#define C_ 1024
#define H_ 16
#define D_ 64
#define M_ (B_*T_)   // 8192

// ---------------------------------------------------------------------------
// Scratch (__device__ globals; referenced ONLY from device code — host-side
// use of these symbols yields the host shadow (ATS zeros), the round-5/6 bug)
// ---------------------------------------------------------------------------
__device__ float g_q[(size_t)B_*H_*T_*D_];
__device__ float g_k[(size_t)B_*H_*T_*D_];
__device__ float g_v[(size_t)B_*H_*T_*D_];
__device__ float g_y[(size_t)B_*T_*C_];
__device__ __align__(16) unsigned short g_xhi[(size_t)M_*C_];
__device__ __align__(16) unsigned short g_xlo[(size_t)M_*C_];
__device__ __align__(16) unsigned short g_whiT[(size_t)4*C_*C_];  // [slot][n][k]
__device__ __align__(16) unsigned short g_wloT[(size_t)4*C_*C_];

// ---------------------------------------------------------------------------
// Base-target PTX helpers
// ---------------------------------------------------------------------------
__device__ __forceinline__ uint32_t s2u(const void* p) {
    uint32_t a;
    asm("{ .reg .u64 t; cvta.to.shared.u64 t, %1; cvt.u32.u64 %0, t; }" : "=r"(a) : "l"(p));
    return a;
}

__device__ __forceinline__ void ldsm_x4(uint32_t addr, uint32_t* r) {
    asm volatile("ldmatrix.sync.aligned.m8n8.x4.shared.b16 {%0,%1,%2,%3}, [%4];"
                 : "=r"(r[0]), "=r"(r[1]), "=r"(r[2]), "=r"(r[3]) : "r"(addr));
}
__device__ __forceinline__ void ldsm_x4t(uint32_t addr, uint32_t* r) {
    asm volatile("ldmatrix.sync.aligned.m8n8.x4.trans.shared.b16 {%0,%1,%2,%3}, [%4];"
                 : "=r"(r[0]), "=r"(r[1]), "=r"(r[2]), "=r"(r[3]) : "r"(addr));
}

__device__ __forceinline__ void mma_bf16(float* c, const uint32_t* a, uint32_t b0, uint32_t b1) {
    asm("mma.sync.aligned.m16n8k16.row.col.f32.bf16.bf16.f32 "
        "{%0,%1,%2,%3}, {%4,%5,%6,%7}, {%8,%9}, {%0,%1,%2,%3};"
        : "+f"(c[0]), "+f"(c[1]), "+f"(c[2]), "+f"(c[3])
        : "r"(a[0]), "r"(a[1]), "r"(a[2]), "r"(a[3]), "r"(b0), "r"(b1));
}

__device__ __forceinline__ void cp16(uint32_t saddr, const void* g) {
    asm volatile("cp.async.cg.shared.global [%0], [%1], 16;" :: "r"(saddr), "l"(g));
}

// pack two floats to bf16x2: low 16 bits = lo arg, high 16 bits = hi arg
__device__ __forceinline__ uint32_t packbf(float lo, float hi) {
    uint32_t r;
    asm("cvt.rn.bf16x2.f32 %0, %1, %2;" : "=r"(r) : "f"(hi), "f"(lo));
    return r;
}

// ---------------------------------------------------------------------------
// Conversion pre-passes. SRC=0: from param; SRC=1: from g_y.
// ---------------------------------------------------------------------------
template<int SRC>
__global__ __launch_bounds__(256) void conv_x_k(const float* __restrict__ in, int n4)
{
    int i = blockIdx.x * blockDim.x + threadIdx.x;
    if (i >= n4) return;
    const float* src = (SRC == 1) ? (const float*)g_y : in;
    float4 v = ((const float4*)src)[i];
    uint32_t h0 = packbf(v.x, v.y);
    uint32_t h1 = packbf(v.z, v.w);
    float r0 = v.x - __uint_as_float(h0 << 16);
    float r1 = v.y - __uint_as_float(h0 & 0xFFFF0000u);
    float r2 = v.z - __uint_as_float(h1 << 16);
    float r3 = v.w - __uint_as_float(h1 & 0xFFFF0000u);
    ((uint2*)g_xhi)[i] = make_uint2(h0, h1);
    ((uint2*)g_xlo)[i] = make_uint2(packbf(r0, r1), packbf(r2, r3));
}

// W[k][n] -> WT hi/lo [n][k]
__global__ void conv_w_t_k(const float* __restrict__ W, int slot)
{
    __shared__ float tile[32][33];
    const int n0 = blockIdx.x * 32, k0 = blockIdx.y * 32;
    const int tx = threadIdx.x, ty = threadIdx.y;
    unsigned short* hiT = g_whiT + (size_t)slot * C_ * C_;
    unsigned short* loT = g_wloT + (size_t)slot * C_ * C_;
    for (int r = ty; r < 32; r += 8)
        tile[r][tx] = W[(size_t)(k0 + r) * C_ + n0 + tx];
    __syncthreads();
    for (int r = ty; r < 32; r += 8) {
        float v = tile[tx][r];
        __nv_bfloat16 h = __float2bfloat16_rn(v);
        float res = v - __bfloat162float(h);
        size_t o = (size_t)(n0 + r) * C_ + k0 + tx;
        hiT[o] = __bfloat16_as_ushort(h);
        loT[o] = __bfloat16_as_ushort(__float2bfloat16_rn(res));
    }
}

// ---------------------------------------------------------------------------
// GEMM via mma.sync (validated round 7, unchanged)
// ---------------------------------------------------------------------------
template<int DST>
__global__ __launch_bounds__(256)
void gemm_mma(const float* __restrict__ bias, float* __restrict__ OutP)
{
    extern __shared__ __align__(16) char sm[];
    const uint32_t smb = s2u(sm);
    const int tid = threadIdx.x, lane = tid & 31, wid = tid >> 5;
    const int warp_m = wid >> 2, warp_n = wid & 3;
    const int m0 = blockIdx.x * 128, n0 = blockIdx.y * 128;

    const unsigned short* Ahi = g_xhi;
    const unsigned short* Alo = g_xlo;
    const unsigned short* Bhi = g_whiT + (size_t)DST * C_ * C_;
    const unsigned short* Blo = g_wloT + (size_t)DST * C_ * C_;

    const unsigned short* gsrc[8];
    uint32_t sdst[8];
#pragma unroll
    for (int i = 0; i < 8; i++) {
        const int op  = i >> 1;
        const int row = (tid >> 2) + (i & 1) * 64;
        const int seg = tid & 3;
        const unsigned short* base = (op == 0) ? Ahi : (op == 1) ? Alo : (op == 2) ? Bhi : Blo;
        const int grow = ((op < 2) ? m0 : n0) + row;
        gsrc[i] = base + (size_t)grow * C_ + seg * 8;
        sdst[i] = smb + op * 10240 + row * 80 + seg * 16;
    }

    float c[4][4][4];
#pragma unroll
    for (int mt = 0; mt < 4; mt++)
#pragma unroll
        for (int nt = 0; nt < 4; nt++)
#pragma unroll
            for (int e = 0; e < 4; e++) c[mt][nt][e] = 0.f;

#pragma unroll
    for (int i = 0; i < 8; i++) cp16(sdst[i], gsrc[i]);
    asm volatile("cp.async.commit_group;");

    for (int it = 0; it < 32; ++it) {
        const int st = it & 1;
        if (it + 1 < 32) {
            const int ns = (it + 1) & 1;
#pragma unroll
            for (int i = 0; i < 8; i++) cp16(sdst[i] + ns * 40960, gsrc[i] + (it + 1) * 32);
            asm volatile("cp.async.commit_group;");
            asm volatile("cp.async.wait_group 1;");
        } else {
            asm volatile("cp.async.wait_group 0;");
        }
        __syncthreads();

        const uint32_t sb = smb + st * 40960;
#pragma unroll
        for (int kk = 0; kk < 2; kk++) {
            uint32_t ah[4][4], al[4][4], bh[4][2], bl[4][2];
#pragma unroll
            for (int mt = 0; mt < 4; mt++) {
                int row = warp_m * 64 + mt * 16 + (lane & 7) + ((lane >> 3) & 1) * 8;
                uint32_t byte = (uint32_t)(row * 80 + kk * 32 + (lane >> 4) * 16);
                ldsm_x4(sb + byte, ah[mt]);
                ldsm_x4(sb + 10240 + byte, al[mt]);
            }
#pragma unroll
            for (int p = 0; p < 2; p++) {
                int row = warp_n * 32 + p * 16 + (lane & 7) + ((lane >> 3) & 1) * 8;
                uint32_t byte = (uint32_t)(row * 80 + kk * 32 + (lane >> 4) * 16);
                uint32_t r[4], u[4];
                ldsm_x4(sb + 20480 + byte, r);
                ldsm_x4(sb + 30720 + byte, u);
                bh[2*p][0] = r[0]; bh[2*p][1] = r[2];
                bh[2*p+1][0] = r[1]; bh[2*p+1][1] = r[3];
                bl[2*p][0] = u[0]; bl[2*p][1] = u[2];
                bl[2*p+1][0] = u[1]; bl[2*p+1][1] = u[3];
            }
#pragma unroll
            for (int mt = 0; mt < 4; mt++)
#pragma unroll
                for (int nt = 0; nt < 4; nt++) {
                    mma_bf16(c[mt][nt], ah[mt], bh[nt][0], bh[nt][1]);
                    mma_bf16(c[mt][nt], ah[mt], bl[nt][0], bl[nt][1]);
                    mma_bf16(c[mt][nt], al[mt], bh[nt][0], bh[nt][1]);
                }
        }
        __syncthreads();
    }

#pragma unroll
    for (int mt = 0; mt < 4; mt++) {
        const int r = m0 + warp_m * 64 + mt * 16 + (lane >> 2);
#pragma unroll
        for (int nt = 0; nt < 4; nt++) {
            const int col = n0 + warp_n * 32 + nt * 8 + (lane & 3) * 2;
            const float bb0 = bias[col], bb1 = bias[col + 1];
#pragma unroll
            for (int half = 0; half < 2; half++) {
                const int m = r + half * 8;
                float v0 = c[mt][nt][half * 2 + 0] + bb0;
                float v1 = c[mt][nt][half * 2 + 1] + bb1;
                if (DST == 3) {
                    *(float2*)(OutP + (size_t)m * C_ + col) = make_float2(v0, v1);
                } else {
                    float* O = (DST == 0) ? g_q : (DST == 1) ? g_k : g_v;
                    const int b = m >> 11, t = m & (T_ - 1);
                    const int h = col >> 6, d = col & 63;
                    *(float2*)(O + (((size_t)(b * H_ + h)) * T_ + t) * D_ + d) = make_float2(v0, v1);
                }
            }
        }
    }
}

// ---------------------------------------------------------------------------
// Causal flash attention via mma.sync. 4 warps, 64x64 tiles, D=64.
// Reads fp32 g_q/g_k/g_v, converts tiles to split-bf16 in smem (Q scaled 1/8).
// smem: KH | KL | VH | VL, 64 rows x 144B stride each. Q staged in KH/KL.
// ---------------------------------------------------------------------------
__global__ __launch_bounds__(128)
void attn_mma()
{
    __shared__ __align__(16) char sm[4 * 64 * 144];
    const uint32_t smb = s2u(sm);
    const int tid = threadIdx.x, lane = tid & 31, warp = tid >> 5;
    const int qb = blockIdx.x, bh = blockIdx.y;

    const float* Qg = g_q + (size_t)bh * T_ * D_ + (size_t)qb * 64 * D_;
    const float* Kg = g_k + (size_t)bh * T_ * D_;
    const float* Vg = g_v + (size_t)bh * T_ * D_;

    // ---- stage Q tile (scaled by 1/8), split hi/lo into KH/KL buffers ----
#pragma unroll
    for (int i = 0; i < 8; i++) {
        int idx = i * 128 + tid;                  // float4 index, 1024 total
        float4 v = ((const float4*)Qg)[idx];
        v.x *= 0.125f; v.y *= 0.125f; v.z *= 0.125f; v.w *= 0.125f;
        uint32_t h0 = packbf(v.x, v.y), h1 = packbf(v.z, v.w);
        uint32_t l0 = packbf(v.x - __uint_as_float(h0 << 16),
                             v.y - __uint_as_float(h0 & 0xFFFF0000u));
        uint32_t l1 = packbf(v.z - __uint_as_float(h1 << 16),
                             v.w - __uint_as_float(h1 & 0xFFFF0000u));
        int row = idx >> 4, c8 = (idx & 15) * 8;
        *(uint2*)(sm + row * 144 + c8) = make_uint2(h0, h1);           // KH
        *(uint2*)(sm + 9216 + row * 144 + c8) = make_uint2(l0, l1);    // KL
    }
    __syncthreads();

    uint32_t qhf[4][4], qlf[4][4];
#pragma unroll
    for (int kk = 0; kk < 4; kk++) {
        int row = warp * 16 + (lane & 7) + ((lane >> 3) & 1) * 8;
        uint32_t byte = (uint32_t)(row * 144 + kk * 32 + (lane >> 4) * 16);
        ldsm_x4(smb + byte, qhf[kk]);
        ldsm_x4(smb + 9216 + byte, qlf[kk]);
    }
    __syncthreads();

    float o[8][4];
#pragma unroll
    for (int j = 0; j < 8; j++)
#pragma unroll
        for (int e = 0; e < 4; e++) o[j][e] = 0.f;
    float m0r = -1e30f, m1r = -1e30f, l0r = 0.f, l1r = 0.f;

    for (int kb = 0; kb <= qb; kb++) {
        // ---- load K/V fp32, convert to split-bf16 smem tiles ----
#pragma unroll
        for (int i = 0; i < 8; i++) {
            int idx = i * 128 + tid;
            int row = idx >> 4, c8 = (idx & 15) * 8;
            {
                float4 v = ((const float4*)(Kg + (size_t)kb * 64 * D_))[idx];
                uint32_t h0 = packbf(v.x, v.y), h1 = packbf(v.z, v.w);
                uint32_t l0 = packbf(v.x - __uint_as_float(h0 << 16),
                                     v.y - __uint_as_float(h0 & 0xFFFF0000u));
                uint32_t l1 = packbf(v.z - __uint_as_float(h1 << 16),
                                     v.w - __uint_as_float(h1 & 0xFFFF0000u));
                *(uint2*)(sm + row * 144 + c8) = make_uint2(h0, h1);
                *(uint2*)(sm + 9216 + row * 144 + c8) = make_uint2(l0, l1);
            }
            {
                float4 v = ((const float4*)(Vg + (size_t)kb * 64 * D_))[idx];
                uint32_t h0 = packbf(v.x, v.y), h1 = packbf(v.z, v.w);
                uint32_t l0 = packbf(v.x - __uint_as_float(h0 << 16),
                                     v.y - __uint_as_float(h0 & 0xFFFF0000u));
                uint32_t l1 = packbf(v.z - __uint_as_float(h1 << 16),
                                     v.w - __uint_as_float(h1 & 0xFFFF0000u));
                *(uint2*)(sm + 18432 + row * 144 + c8) = make_uint2(h0, h1);
                *(uint2*)(sm + 27648 + row * 144 + c8) = make_uint2(l0, l1);
            }
        }
        __syncthreads();

        // ---- S = Q K^T (3-term split) ----
        float s[8][4];
#pragma unroll
        for (int j = 0; j < 8; j++)
#pragma unroll
            for (int e = 0; e < 4; e++) s[j][e] = 0.f;

#pragma unroll
        for (int kk = 0; kk < 4; kk++) {
            uint32_t kh[8][2], kl[8][2];
#pragma unroll
            for (int p = 0; p < 4; p++) {
                int row = p * 16 + (lane & 7) + ((lane >> 3) & 1) * 8;
                uint32_t byte = (uint32_t)(row * 144 + kk * 32 + (lane >> 4) * 16);
                uint32_t r[4], u[4];
                ldsm_x4(smb + byte, r);          // KH
                ldsm_x4(smb + 9216 + byte, u);   // KL
                kh[2*p][0] = r[0]; kh[2*p][1] = r[2];
                kh[2*p+1][0] = r[1]; kh[2*p+1][1] = r[3];
                kl[2*p][0] = u[0]; kl[2*p][1] = u[2];
                kl[2*p+1][0] = u[1]; kl[2*p+1][1] = u[3];
            }
#pragma unroll
            for (int j = 0; j < 8; j++) {
                mma_bf16(s[j], qhf[kk], kh[j][0], kh[j][1]);
                mma_bf16(s[j], qhf[kk], kl[j][0], kl[j][1]);
                mma_bf16(s[j], qlf[kk], kh[j][0], kh[j][1]);
            }
        }

        // ---- causal mask on diagonal block ----
        if (kb == qb) {
            const int r0 = warp * 16 + (lane >> 2);
#pragma unroll
            for (int j = 0; j < 8; j++) {
#pragma unroll
                for (int e = 0; e < 4; e++) {
                    int col = j * 8 + (lane & 3) * 2 + (e & 1);
                    int row = r0 + (e >> 1) * 8;
                    if (col > row) s[j][e] = -1e30f;
                }
            }
        }

        // ---- online softmax (per-lane rows + quad reduction) ----
        float mt0 = -1e30f, mt1 = -1e30f;
#pragma unroll
        for (int j = 0; j < 8; j++) {
            mt0 = fmaxf(mt0, fmaxf(s[j][0], s[j][1]));
            mt1 = fmaxf(mt1, fmaxf(s[j][2], s[j][3]));
        }
        mt0 = fmaxf(mt0, __shfl_xor_sync(0xffffffffu, mt0, 1));
        mt0 = fmaxf(mt0, __shfl_xor_sync(0xffffffffu, mt0, 2));
        mt1 = fmaxf(mt1, __shfl_xor_sync(0xffffffffu, mt1, 1));
        mt1 = fmaxf(mt1, __shfl_xor_sync(0xffffffffu, mt1, 2));
        const float mn0 = fmaxf(m0r, mt0), mn1 = fmaxf(m1r, mt1);
        const float al0 = __expf(m0r - mn0), al1 = __expf(m1r - mn1);

        float ls0 = 0.f, ls1 = 0.f;
        uint32_t aph[4][4], apl[4][4];
#pragma unroll
        for (int j = 0; j < 8; j++) {
            float p0 = __expf(s[j][0] - mn0);
            float p1 = __expf(s[j][1] - mn0);
            float p2 = __expf(s[j][2] - mn1);
            float p3 = __expf(s[j][3] - mn1);
            ls0 += p0 + p1;
            ls1 += p2 + p3;
            uint32_t h01 = packbf(p0, p1), h23 = packbf(p2, p3);
            float e0 = p0 - __uint_as_float(h01 << 16);
            float e1 = p1 - __uint_as_float(h01 & 0xFFFF0000u);
            float e2 = p2 - __uint_as_float(h23 << 16);
            float e3 = p3 - __uint_as_float(h23 & 0xFFFF0000u);
            uint32_t l01 = packbf(e0, e1), l23 = packbf(e2, e3);
            const int kk = j >> 1;
            if ((j & 1) == 0) {
                aph[kk][0] = h01; aph[kk][1] = h23;
                apl[kk][0] = l01; apl[kk][1] = l23;
            } else {
                aph[kk][2] = h01; aph[kk][3] = h23;
                apl[kk][2] = l01; apl[kk][3] = l23;
            }
        }
        ls0 += __shfl_xor_sync(0xffffffffu, ls0, 1);
        ls0 += __shfl_xor_sync(0xffffffffu, ls0, 2);
        ls1 += __shfl_xor_sync(0xffffffffu, ls1, 1);
        ls1 += __shfl_xor_sync(0xffffffffu, ls1, 2);
        l0r = l0r * al0 + ls0;
        l1r = l1r * al1 + ls1;
        m0r = mn0; m1r = mn1;

#pragma unroll
        for (int j = 0; j < 8; j++) {
            o[j][0] *= al0; o[j][1] *= al0;
            o[j][2] *= al1; o[j][3] *= al1;
        }

        // ---- O += P V (3-term split) ----
#pragma unroll
        for (int kk = 0; kk < 4; kk++) {
#pragma unroll
            for (int j = 0; j < 8; j += 2) {
                int row = kk * 16 + (lane & 7) + ((lane >> 3) & 1) * 8;
                uint32_t byte = (uint32_t)(row * 144 + (j + (lane >> 4)) * 16);
                uint32_t r[4], u[4];
                ldsm_x4t(smb + 18432 + byte, r);   // VH
                ldsm_x4t(smb + 27648 + byte, u);   // VL
                mma_bf16(o[j],     aph[kk], r[0], r[1]);
                mma_bf16(o[j],     aph[kk], u[0], u[1]);
                mma_bf16(o[j],     apl[kk], r[0], r[1]);
                mma_bf16(o[j + 1], aph[kk], r[2], r[3]);
                mma_bf16(o[j + 1], aph[kk], u[2], u[3]);
                mma_bf16(o[j + 1], apl[kk], r[2], r[3]);
            }
        }
        __syncthreads();
    }

    // ---- epilogue: normalize, fp32 write to g_y [B,T,C] ----
    const float inv0 = 1.f / l0r, inv1 = 1.f / l1r;
    const int b = bh >> 4, h = bh & 15;
    const int r0g = qb * 64 + warp * 16 + (lane >> 2);
#pragma unroll
    for (int j = 0; j < 8; j++) {
        const int col = h * 64 + j * 8 + (lane & 3) * 2;
        size_t i0 = ((size_t)b * T_ + r0g) * C_ + col;
        size_t i1 = ((size_t)b * T_ + r0g + 8) * C_ + col;
        *(float2*)(g_y + i0) = make_float2(o[j][0] * inv0, o[j][1] * inv0);
        *(float2*)(g_y + i1) = make_float2(o[j][2] * inv1, o[j][3] * inv1);
    }
}

// ---------------------------------------------------------------------------
extern "C" void kernel_launch(void* const* d_in, const int* in_sizes, int n_in,
                              void* d_out, int out_size)
{
    const float* x  = (const float*)d_in[0];
    const float* Wk = (const float*)d_in[1];
    const float* bk = (const float*)d_in[2];
    const float* Wq = (const float*)d_in[3];
    const float* bq = (const float*)d_in[4];
    const float* Wv = (const float*)d_in[5];
    const float* bv = (const float*)d_in[6];
    const float* Wp = (const float*)d_in[7];
    const float* bp = (const float*)d_in[8];
    float* out = (float*)d_out;

    const int n4 = M_ * C_ / 4;
    conv_x_k<0><<<(n4 + 255) / 256, 256>>>(x, n4);

    dim3 tg(32, 32), tb(32, 8);
    conv_w_t_k<<<tg, tb>>>(Wq, 0);
    conv_w_t_k<<<tg, tb>>>(Wk, 1);
    conv_w_t_k<<<tg, tb>>>(Wv, 2);
    conv_w_t_k<<<tg, tb>>>(Wp, 3);

    const int smem_g = 81920;
    cudaFuncSetAttribute(gemm_mma<0>, cudaFuncAttributeMaxDynamicSharedMemorySize, smem_g);
    cudaFuncSetAttribute(gemm_mma<1>, cudaFuncAttributeMaxDynamicSharedMemorySize, smem_g);
    cudaFuncSetAttribute(gemm_mma<2>, cudaFuncAttributeMaxDynamicSharedMemorySize, smem_g);
    cudaFuncSetAttribute(gemm_mma<3>, cudaFuncAttributeMaxDynamicSharedMemorySize, smem_g);

    dim3 gg(M_ / 128, C_ / 128);
    gemm_mma<0><<<gg, 256, smem_g>>>(bq, nullptr);
    gemm_mma<1><<<gg, 256, smem_g>>>(bk, nullptr);
    gemm_mma<2><<<gg, 256, smem_g>>>(bv, nullptr);

    attn_mma<<<dim3(T_ / 64, B_ * H_), 128>>>();

    conv_x_k<1><<<(n4 + 255) / 256, 256>>>(nullptr, n4);
    gemm_mma<3><<<gg, 256, smem_g>>>(bp, out);
}